// round 8
// baseline (speedup 1.0000x reference)
#include <cuda_runtime.h>
#include <cuda_bf16.h>
#include <mma.h>
#include <cstdint>

using namespace nvcuda;

// Problem constants
#define BATCH  4
#define SEQ    4096
#define DMODEL 1024
#define NHEAD  16
#define HDIM   64
#define DFF    4096
#define WIN    512
#define MROWS  (BATCH*SEQ)          // 16384

// ---------------- scratch (device globals; no allocations allowed) ----------
static __device__ float g_q   [(size_t)MROWS * DMODEL];
static __device__ float g_k   [(size_t)MROWS * DMODEL];
static __device__ float g_v   [(size_t)MROWS * DMODEL];
static __device__ float g_attn[(size_t)MROWS * DMODEL];
static __device__ float g_xln [(size_t)MROWS * DMODEL];
static __device__ float g_h   [(size_t)MROWS * DFF];
static __device__ float g_y   [(size_t)MROWS * DMODEL];
// tf32-rounded copies
static __device__ float g_srcr[(size_t)MROWS * DMODEL];
static __device__ float g_wqkv[(size_t)3 * DMODEL * DMODEL];
static __device__ float g_bqkv[3 * DMODEL];
static __device__ float g_w1r [(size_t)DFF * DMODEL];
static __device__ float g_w2r [(size_t)DMODEL * DFF];

__device__ __forceinline__ float tf32r(float x) {
    float y;
    asm("cvt.rna.tf32.f32 %0, %1;" : "=f"(y) : "f"(x));
    return y;
}

__device__ __forceinline__ void cp_async16(float* dst, const float* src) {
    unsigned int d = (unsigned int)__cvta_generic_to_shared(dst);
    asm volatile("cp.async.cg.shared.global [%0], [%1], 16;\n" :: "r"(d), "l"(src));
}

// ============================================================================
// Fused prepass: tf32-round src + pack/round {wq,wk,wv}->wqkv, w1, w2,
// pack {bq,bk,bv}->bqkv (not rounded). One launch.
// Regions (float4 indices):
//   [0, 4194304)           src -> srcr
//   [4194304, 4456448)     wq  -> wqkv[0]
//   [4456448, 4718592)     wk  -> wqkv[1M floats]
//   [4718592, 4980736)     wv  -> wqkv[2M floats]
//   [4980736, 6029312)     w1  -> w1r
//   [6029312, 7077888)     w2  -> w2r
//   [7077888, 7078656)     bias pack (256 f4 each)
// ============================================================================
#define RA_TOTAL 7078656
__global__ __launch_bounds__(256)
void round_all(const float* __restrict__ src,
               const float* __restrict__ wq, const float* __restrict__ wk,
               const float* __restrict__ wv, const float* __restrict__ w1,
               const float* __restrict__ w2, const float* __restrict__ bq,
               const float* __restrict__ bk, const float* __restrict__ bv,
               float* __restrict__ srcr, float* __restrict__ wqkv,
               float* __restrict__ w1r, float* __restrict__ w2r,
               float* __restrict__ bqkv)
{
    long long i = (long long)blockIdx.x * 256 + threadIdx.x;
    if (i >= RA_TOTAL) return;
    const float* in;
    float* outp;
    bool rnd = true;
    if (i < 4194304)      { in = src + i * 4;               outp = srcr + i * 4; }
    else if (i < 4456448) { long long j = i - 4194304; in = wq + j * 4; outp = wqkv + j * 4; }
    else if (i < 4718592) { long long j = i - 4456448; in = wk + j * 4; outp = wqkv + 1048576 + j * 4; }
    else if (i < 4980736) { long long j = i - 4718592; in = wv + j * 4; outp = wqkv + 2097152 + j * 4; }
    else if (i < 6029312) { long long j = i - 4980736; in = w1 + j * 4; outp = w1r + j * 4; }
    else if (i < 7077888) { long long j = i - 6029312; in = w2 + j * 4; outp = w2r + j * 4; }
    else {
        long long j = i - 7077888;   // 0..767
        rnd = false;
        if (j < 256)      { in = bq + j * 4;         outp = bqkv + j * 4; }
        else if (j < 512) { in = bk + (j - 256) * 4; outp = bqkv + 1024 + (j - 256) * 4; }
        else              { in = bv + (j - 512) * 4; outp = bqkv + 2048 + (j - 512) * 4; }
    }
    float4 x = *(const float4*)in;
    if (rnd) { x.x = tf32r(x.x); x.y = tf32r(x.y); x.z = tf32r(x.z); x.w = tf32r(x.w); }
    *(float4*)outp = x;
}

// ============================================================================
// Big-tile TN GEMM: C[M,N] = A[M,K] @ W[N,K]^T (+ epilogue)
// Block tile 256x128, BK=32, 8 warps as 4(m) x 2(n), warp tile 64x64.
// cp.async double-buffered; inputs pre-rounded tf32 (no cvt in mainloop).
//   MODE 0: +bias(packed), round, scatter fused QKV -> q/k/v [B,H,S,d]
//   MODE 1: +bias, ReLU, round (FFN1)
//   MODE 2: +bias, +extra residual (FFN2)
// Padding 36 floats (144B): 16B-aligned, 2-way bank phase (vs 4-way at 40).
// ============================================================================
#define BM 256
#define BN 128
#define BKT 32
#define LDT 36
#define STG_A (BM * LDT)            // 9216 floats
#define STG   ((BM + BN) * LDT)     // 13824 floats per stage
#define BIG_SMEM (2 * STG * (int)sizeof(float))   // 110592 B

template <int MODE>
__global__ __launch_bounds__(256, 1)
void gemm_big(const float* __restrict__ A, const float* __restrict__ W,
              const float* __restrict__ bias, const float* __restrict__ extra,
              float* __restrict__ out0, float* __restrict__ out1,
              float* __restrict__ out2, int K, int N)
{
    extern __shared__ float sm[];
    const int tid = threadIdx.x;
    const int wid = tid >> 5;
    const int lane = tid & 31;
    const int wm = wid & 3;     // 0..3 (64-row strips)
    const int wn = wid >> 2;    // 0..1 (64-col strips)

    wmma::fragment<wmma::accumulator, 16, 16, 8, float> acc[4][4];
#pragma unroll
    for (int i = 0; i < 4; i++)
#pragma unroll
        for (int j = 0; j < 4; j++)
            wmma::fill_fragment(acc[i][j], 0.0f);

    const float* Ablk = A + (size_t)blockIdx.y * BM * K;
    const float* Wblk = W + (size_t)blockIdx.x * BN * K;

    auto load_stage = [&](int s, int kt) {
        float* As = sm + s * STG;
        float* Ws = As + STG_A;
#pragma unroll
        for (int p = 0; p < 8; p++) {          // A: 256 rows x 32
            int c = tid + p * 256;             // 0..2047
            int r = c >> 3, c16 = (c & 7) << 2;
            cp_async16(As + r * LDT + c16, Ablk + (size_t)r * K + kt + c16);
        }
#pragma unroll
        for (int p = 0; p < 4; p++) {          // W: 128 rows x 32
            int c = tid + p * 256;             // 0..1023
            int r = c >> 3, c16 = (c & 7) << 2;
            cp_async16(Ws + r * LDT + c16, Wblk + (size_t)r * K + kt + c16);
        }
        asm volatile("cp.async.commit_group;\n");
    };

    const int T = K / BKT;
    load_stage(0, 0);

    for (int t = 0; t < T; t++) {
        const int cur = t & 1;
        if (t + 1 < T) {
            load_stage(cur ^ 1, (t + 1) * BKT);
            asm volatile("cp.async.wait_group 1;\n");
        } else {
            asm volatile("cp.async.wait_group 0;\n");
        }
        __syncthreads();

        const float* As = sm + cur * STG;
        const float* Ws = As + STG_A;
#pragma unroll
        for (int kk = 0; kk < BKT; kk += 8) {
            wmma::fragment<wmma::matrix_a, 16, 16, 8, wmma::precision::tf32, wmma::row_major> af[4];
#pragma unroll
            for (int i = 0; i < 4; i++)
                wmma::load_matrix_sync(af[i], As + (wm * 64 + i * 16) * LDT + kk, LDT);
#pragma unroll
            for (int j = 0; j < 4; j++) {
                wmma::fragment<wmma::matrix_b, 16, 16, 8, wmma::precision::tf32, wmma::col_major> bf;
                wmma::load_matrix_sync(bf, Ws + (wn * 64 + j * 16) * LDT + kk, LDT);
#pragma unroll
                for (int i = 0; i < 4; i++)
                    wmma::mma_sync(acc[i][j], af[i], bf, acc[i][j]);
            }
        }
        __syncthreads();
    }

    // Per-warp epilogue: stage 64x32 halves in a private smem strip.
    const int m0 = blockIdx.y * BM + wm * 64;
    const int n0 = blockIdx.x * BN + wn * 64;
    float* Cw = sm + wid * (64 * LDT);   // 2304 floats per warp (aliases stages)

#pragma unroll
    for (int j2 = 0; j2 < 2; j2++) {
#pragma unroll
        for (int i = 0; i < 4; i++)
#pragma unroll
            for (int jj = 0; jj < 2; jj++)
                wmma::store_matrix_sync(Cw + (i * 16) * LDT + jj * 16,
                                        acc[i][j2 * 2 + jj], LDT, wmma::mem_row_major);
        __syncwarp();

        const int nb = n0 + j2 * 32;
#pragma unroll
        for (int rr = 0; rr < 2; rr++) {
            int r = lane + rr * 32;
            int m = m0 + r;
#pragma unroll
            for (int c4 = 0; c4 < 8; c4++) {
                int n = nb + c4 * 4;
                float4 c = *(float4*)(Cw + r * LDT + c4 * 4);
                float4 bb = *(const float4*)(bias + n);
                c.x += bb.x; c.y += bb.y; c.z += bb.z; c.w += bb.w;
                if constexpr (MODE == 1) {
                    c.x = tf32r(fmaxf(c.x, 0.f)); c.y = tf32r(fmaxf(c.y, 0.f));
                    c.z = tf32r(fmaxf(c.z, 0.f)); c.w = tf32r(fmaxf(c.w, 0.f));
                    *(float4*)(out0 + (size_t)m * N + n) = c;
                } else if constexpr (MODE == 2) {
                    float4 e = *(const float4*)(extra + (size_t)m * N + n);
                    c.x += e.x; c.y += e.y; c.z += e.z; c.w += e.w;
                    *(float4*)(out0 + (size_t)m * N + n) = c;
                } else {
                    c.x = tf32r(c.x); c.y = tf32r(c.y); c.z = tf32r(c.z); c.w = tf32r(c.w);
                    int mat = n >> 10;
                    int nl  = n & 1023;
                    int h   = nl >> 6;
                    int dd  = nl & (HDIM - 1);
                    int bi  = m >> 12;
                    int s   = m & (SEQ - 1);
                    float* dst = (mat == 0) ? out0 : (mat == 1) ? out1 : out2;
                    size_t o = (((size_t)bi * NHEAD + h) * SEQ + s) * HDIM + dd;
                    *(float4*)(dst + o) = c;
                }
            }
        }
        __syncwarp();
    }
}

// ============================================================================
// Windowed causal flash attention: register-Q, in-place accumulator.
// q/k/v pre-rounded tf32 -> no cvt in matmul loops. P rounded at softmax.
// ============================================================================
#define ALD 72
#define ACCLD 68
#define ATTN_SMEM ((3 * 64 * ALD + 64 * ACCLD + 2 * 64) * (int)sizeof(float))

__global__ __launch_bounds__(256, 2)
void attn_kernel(const float* __restrict__ q, const float* __restrict__ k,
                 const float* __restrict__ v, float* __restrict__ out)
{
    const int idx = blockIdx.x;
    const int qc = idx & 7;
    const int w  = (idx >> 3) & 7;
    const int h  = (idx >> 6) & 15;
    const int b  = idx >> 10;

    extern __shared__ float sm[];
    float* k_s  = sm;
    float* v_s  = k_s + 64 * ALD;
    float* s_s  = v_s + 64 * ALD;
    float* accs = s_s + 64 * ALD;
    float* m_s  = accs + 64 * ACCLD;
    float* l_s  = m_s + 64;

    const int tid = threadIdx.x;
    const int wid = tid >> 5;
    const int wm  = wid & 1;
    const int wn  = wid >> 1;
    const size_t headbase = ((size_t)(b * NHEAD + h)) * SEQ * HDIM;
    const int q0 = w * WIN + qc * 64;

    const int tr = tid >> 4;
    const int tc = (tid & 15) << 2;

    wmma::fragment<wmma::matrix_a, 16, 16, 8, wmma::precision::tf32, wmma::row_major> a_q[2][8];
    {
        const float* qg = q + headbase + (size_t)q0 * HDIM;
#pragma unroll
        for (int i = 0; i < 2; i++)
#pragma unroll
            for (int ks = 0; ks < 8; ks++) {
                wmma::load_matrix_sync(a_q[i][ks],
                                       qg + (size_t)(wm * 32 + i * 16) * HDIM + ks * 8, HDIM);
#pragma unroll
                for (int e = 0; e < a_q[i][ks].num_elements; e++)
                    a_q[i][ks].x[e] = a_q[i][ks].x[e] * 0.125f;
            }
    }

#pragma unroll
    for (int p = 0; p < 4; p++) {
        int r = tr + p * 16;
        *(float4*)(accs + r * ACCLD + tc) = make_float4(0.f, 0.f, 0.f, 0.f);
    }
    if (tid < 64) { m_s[tid] = -1e30f; l_s[tid] = 0.f; }

    const int kstart = (w == 0) ? 0 : (w - 1) * WIN;
    const int kend   = q0 + 64;

    for (int kc = kstart; kc < kend; kc += 64) {
        __syncthreads();

        const float* kg = k + headbase + (size_t)kc * HDIM;
        const float* vg = v + headbase + (size_t)kc * HDIM;
#pragma unroll
        for (int p = 0; p < 4; p++) {
            int r = tr + p * 16;
            *(float4*)(k_s + r * ALD + tc) = *(const float4*)(kg + r * HDIM + tc);
            *(float4*)(v_s + r * ALD + tc) = *(const float4*)(vg + r * HDIM + tc);
        }
        __syncthreads();

        {
            wmma::fragment<wmma::accumulator, 16, 16, 8, float> sacc[2];
#pragma unroll
            for (int i = 0; i < 2; i++) wmma::fill_fragment(sacc[i], 0.0f);
#pragma unroll
            for (int ks = 0; ks < 8; ks++) {
                wmma::fragment<wmma::matrix_b, 16, 16, 8, wmma::precision::tf32, wmma::col_major> bf;
                wmma::load_matrix_sync(bf, k_s + (wn * 16) * ALD + ks * 8, ALD);
#pragma unroll
                for (int i = 0; i < 2; i++)
                    wmma::mma_sync(sacc[i], a_q[i][ks], bf, sacc[i]);
            }
#pragma unroll
            for (int i = 0; i < 2; i++)
                wmma::store_matrix_sync(s_s + (wm * 32 + i * 16) * ALD + wn * 16,
                                        sacc[i], ALD, wmma::mem_row_major);
        }
        __syncthreads();

        {
            const bool diag = (kc == q0);
            const int r  = tid >> 2;
            const int c0 = (tid & 3) << 4;
            float* srow = s_s + r * ALD + c0;
            float mloc = -1e30f;
            if (diag) {
#pragma unroll
                for (int t = 0; t < 16; t++) {
                    float sv = srow[t];
                    if (c0 + t > r) sv = -1e30f;
                    srow[t] = sv;
                    mloc = fmaxf(mloc, sv);
                }
            } else {
#pragma unroll
                for (int t = 0; t < 16; t++) mloc = fmaxf(mloc, srow[t]);
            }
            mloc = fmaxf(mloc, __shfl_xor_sync(0xffffffffu, mloc, 1));
            mloc = fmaxf(mloc, __shfl_xor_sync(0xffffffffu, mloc, 2));
            float mold = m_s[r];
            float mnew = fmaxf(mold, mloc);
            float ssum = 0.f;
#pragma unroll
            for (int t = 0; t < 16; t++) {
                float pz = tf32r(__expf(srow[t] - mnew));
                srow[t] = pz;
                ssum += pz;
            }
            ssum += __shfl_xor_sync(0xffffffffu, ssum, 1);
            ssum += __shfl_xor_sync(0xffffffffu, ssum, 2);
            float alpha = __expf(mold - mnew);
            if ((tid & 3) == 0) {
                m_s[r] = mnew;
                l_s[r] = l_s[r] * alpha + ssum;
            }
            float* arow = accs + r * ACCLD + c0;
#pragma unroll
            for (int t = 0; t < 4; t++) {
                float4 a4 = *(float4*)(arow + t * 4);
                a4.x *= alpha; a4.y *= alpha; a4.z *= alpha; a4.w *= alpha;
                *(float4*)(arow + t * 4) = a4;
            }
        }
        __syncthreads();

        {
            wmma::fragment<wmma::accumulator, 16, 16, 8, float> oacc[2];
#pragma unroll
            for (int i = 0; i < 2; i++)
                wmma::load_matrix_sync(oacc[i],
                                       accs + (wm * 32 + i * 16) * ACCLD + wn * 16,
                                       ACCLD, wmma::mem_row_major);
#pragma unroll
            for (int ks = 0; ks < 8; ks++) {
                wmma::fragment<wmma::matrix_b, 16, 16, 8, wmma::precision::tf32, wmma::row_major> bf;
                wmma::load_matrix_sync(bf, v_s + (ks * 8) * ALD + wn * 16, ALD);
#pragma unroll
                for (int i = 0; i < 2; i++) {
                    wmma::fragment<wmma::matrix_a, 16, 16, 8, wmma::precision::tf32, wmma::row_major> af;
                    wmma::load_matrix_sync(af, s_s + (wm * 32 + i * 16) * ALD + ks * 8, ALD);
                    wmma::mma_sync(oacc[i], af, bf, oacc[i]);
                }
            }
#pragma unroll
            for (int i = 0; i < 2; i++)
                wmma::store_matrix_sync(accs + (wm * 32 + i * 16) * ACCLD + wn * 16,
                                        oacc[i], ACCLD, wmma::mem_row_major);
        }
    }
    __syncthreads();

#pragma unroll
    for (int p = 0; p < 4; p++) {
        int r = tr + p * 16;
        float inv = 1.0f / l_s[r];
        float4 ac = *(float4*)(accs + r * ACCLD + tc);
        ac.x *= inv; ac.y *= inv; ac.z *= inv; ac.w *= inv;
        size_t o = ((size_t)(b * SEQ + q0 + r)) * DMODEL + h * HDIM + tc;
        *(float4*)(out + o) = ac;
    }
}

// ============================================================================
// LayerNorm over D=1024. One block per row, 256 threads x float4.
// ROUND=1: output rounded to tf32 (feeds GEMMs).
// ============================================================================
template <int ROUND>
__global__ __launch_bounds__(256)
void ln_kernel(const float* __restrict__ x, const float* __restrict__ gw,
               const float* __restrict__ bw, float* __restrict__ out)
{
    __shared__ float red[16];
    __shared__ float stats[2];
    const int row = blockIdx.x;
    const int tid = threadIdx.x;
    const float* xr = x + (size_t)row * DMODEL;

    float4 xv = *(const float4*)(xr + tid * 4);
    float s  = xv.x + xv.y + xv.z + xv.w;
    float s2 = xv.x * xv.x + xv.y * xv.y + xv.z * xv.z + xv.w * xv.w;
#pragma unroll
    for (int o = 16; o > 0; o >>= 1) {
        s  += __shfl_xor_sync(0xffffffffu, s, o);
        s2 += __shfl_xor_sync(0xffffffffu, s2, o);
    }
    if ((tid & 31) == 0) { red[tid >> 5] = s; red[8 + (tid >> 5)] = s2; }
    __syncthreads();
    if (tid == 0) {
        float ts = 0.f, ts2 = 0.f;
#pragma unroll
        for (int i = 0; i < 8; i++) { ts += red[i]; ts2 += red[8 + i]; }
        float mu  = ts * (1.0f / DMODEL);
        float var = ts2 * (1.0f / DMODEL) - mu * mu;
        stats[0] = mu;
        stats[1] = rsqrtf(var + 1e-5f);
    }
    __syncthreads();
    float mu = stats[0], rstd = stats[1];
    float4 gv = *(const float4*)(gw + tid * 4);
    float4 bv = *(const float4*)(bw + tid * 4);
    float4 ov;
    ov.x = (xv.x - mu) * rstd * gv.x + bv.x;
    ov.y = (xv.y - mu) * rstd * gv.y + bv.y;
    ov.z = (xv.z - mu) * rstd * gv.z + bv.z;
    ov.w = (xv.w - mu) * rstd * gv.w + bv.w;
    if constexpr (ROUND == 1) {
        ov.x = tf32r(ov.x); ov.y = tf32r(ov.y); ov.z = tf32r(ov.z); ov.w = tf32r(ov.w);
    }
    *(float4*)(out + (size_t)row * DMODEL + tid * 4) = ov;
}

// ============================================================================
extern "C" void kernel_launch(void* const* d_in, const int* in_sizes, int n_in,
                              void* d_out, int out_size)
{
    const float* src = (const float*)d_in[0];
    const float* wq  = (const float*)d_in[1];
    const float* bq  = (const float*)d_in[2];
    const float* wk  = (const float*)d_in[3];
    const float* bk  = (const float*)d_in[4];
    const float* wv  = (const float*)d_in[5];
    const float* bv  = (const float*)d_in[6];
    const float* w1  = (const float*)d_in[7];
    const float* b1  = (const float*)d_in[8];
    const float* w2  = (const float*)d_in[9];
    const float* b2  = (const float*)d_in[10];
    const float* g1  = (const float*)d_in[11];
    const float* be1 = (const float*)d_in[12];
    const float* g2  = (const float*)d_in[13];
    const float* be2 = (const float*)d_in[14];
    float* out = (float*)d_out;

    cudaFuncSetAttribute(gemm_big<0>, cudaFuncAttributeMaxDynamicSharedMemorySize, BIG_SMEM);
    cudaFuncSetAttribute(gemm_big<1>, cudaFuncAttributeMaxDynamicSharedMemorySize, BIG_SMEM);
    cudaFuncSetAttribute(gemm_big<2>, cudaFuncAttributeMaxDynamicSharedMemorySize, BIG_SMEM);
    cudaFuncSetAttribute(attn_kernel, cudaFuncAttributeMaxDynamicSharedMemorySize, ATTN_SMEM);

    float *q, *k, *v, *attn, *xln, *hb, *y;
    float *srcr, *wqkv, *bqkv, *w1r, *w2r;
    cudaGetSymbolAddress((void**)&q,    g_q);
    cudaGetSymbolAddress((void**)&k,    g_k);
    cudaGetSymbolAddress((void**)&v,    g_v);
    cudaGetSymbolAddress((void**)&attn, g_attn);
    cudaGetSymbolAddress((void**)&xln,  g_xln);
    cudaGetSymbolAddress((void**)&hb,   g_h);
    cudaGetSymbolAddress((void**)&y,    g_y);
    cudaGetSymbolAddress((void**)&srcr, g_srcr);
    cudaGetSymbolAddress((void**)&wqkv, g_wqkv);
    cudaGetSymbolAddress((void**)&bqkv, g_bqkv);
    cudaGetSymbolAddress((void**)&w1r,  g_w1r);
    cudaGetSymbolAddress((void**)&w2r,  g_w2r);

    // launch 0: fused prepass
    round_all<<<(RA_TOTAL + 255) / 256, 256>>>(src, wq, wk, wv, w1, w2, bq, bk, bv,
                                               srcr, wqkv, w1r, w2r, bqkv);

    // launch 1: fused QKV GEMM (N = 3072)
    dim3 gQKV(3 * DMODEL / BN, MROWS / BM);        // (24, 64)
    gemm_big<0><<<gQKV, 256, BIG_SMEM>>>(srcr, wqkv, bqkv, nullptr,
                                         q, k, v, DMODEL, 3 * DMODEL);

    // launch 2: attention
    attn_kernel<<<BATCH * NHEAD * (SEQ / 64), 256, ATTN_SMEM>>>(q, k, v, attn);

    // launch 3: LN1 (rounded output)
    ln_kernel<1><<<MROWS, 256>>>(attn, g1, be1, xln);

    // launch 4: FFN1
    dim3 gF1(DFF / BN, MROWS / BM);                // (32, 64)
    gemm_big<1><<<gF1, 256, BIG_SMEM>>>(xln, w1r, b1, nullptr,
                                        hb, nullptr, nullptr, DMODEL, DFF);

    // launch 5: FFN2 (ncu -s 5 lands here)
    dim3 gF2(DMODEL / BN, MROWS / BM);             // (8, 64)
    gemm_big<2><<<gF2, 256, BIG_SMEM>>>(hb, w2r, b2, xln,
                                        y, nullptr, nullptr, DFF, DMODEL);

    // launch 6: LN2 -> out
    ln_kernel<0><<<MROWS, 256>>>(y, g2, be2, out);
}

// round 10
// speedup vs baseline: 1.2615x; 1.2615x over previous
#include <cuda_runtime.h>
#include <cuda_bf16.h>
#include <mma.h>
#include <cstdint>

using namespace nvcuda;

// Problem constants
#define BATCH  4
#define SEQ    4096
#define DMODEL 1024
#define NHEAD  16
#define HDIM   64
#define DFF    4096
#define WIN    512
#define MROWS  (BATCH*SEQ)          // 16384

// ---------------- scratch (device globals; no allocations allowed) ----------
static __device__ float g_q   [(size_t)MROWS * DMODEL];
static __device__ float g_k   [(size_t)MROWS * DMODEL];
static __device__ float g_v   [(size_t)MROWS * DMODEL];
static __device__ float g_attn[(size_t)MROWS * DMODEL];
static __device__ float g_xln [(size_t)MROWS * DMODEL];
static __device__ float g_y   [(size_t)MROWS * DMODEL];
// bf16 split planes (hi/lo)
static __device__ __align__(16) __nv_bfloat16 g_srch[(size_t)MROWS * DMODEL];
static __device__ __align__(16) __nv_bfloat16 g_srcl[(size_t)MROWS * DMODEL];
static __device__ __align__(16) __nv_bfloat16 g_wqkvh[(size_t)3 * DMODEL * DMODEL];
static __device__ __align__(16) __nv_bfloat16 g_wqkvl[(size_t)3 * DMODEL * DMODEL];
static __device__ __align__(16) __nv_bfloat16 g_w1h[(size_t)DFF * DMODEL];
static __device__ __align__(16) __nv_bfloat16 g_w1l[(size_t)DFF * DMODEL];
static __device__ __align__(16) __nv_bfloat16 g_w2h[(size_t)DMODEL * DFF];
static __device__ __align__(16) __nv_bfloat16 g_w2l[(size_t)DMODEL * DFF];
static __device__ __align__(16) __nv_bfloat16 g_xh [(size_t)MROWS * DMODEL];
static __device__ __align__(16) __nv_bfloat16 g_xl [(size_t)MROWS * DMODEL];
static __device__ __align__(16) __nv_bfloat16 g_hh [(size_t)MROWS * DFF];
static __device__ __align__(16) __nv_bfloat16 g_hl [(size_t)MROWS * DFF];
static __device__ float g_bqkv[3 * DMODEL];

__device__ __forceinline__ float tf32r(float x) {
    float y;
    asm("cvt.rna.tf32.f32 %0, %1;" : "=f"(y) : "f"(x));
    return y;
}

__device__ __forceinline__ void cp16(void* dst, const void* src) {
    unsigned int d = (unsigned int)__cvta_generic_to_shared(dst);
    asm volatile("cp.async.cg.shared.global [%0], [%1], 16;\n" :: "r"(d), "l"(src));
}

// split 4 fp32 values into bf16 hi/lo planes (8B store each)
__device__ __forceinline__ void split_store4(float4 x, __nv_bfloat16* hp, __nv_bfloat16* lp) {
    __nv_bfloat16 h0 = __float2bfloat16(x.x);
    __nv_bfloat16 h1 = __float2bfloat16(x.y);
    __nv_bfloat16 h2 = __float2bfloat16(x.z);
    __nv_bfloat16 h3 = __float2bfloat16(x.w);
    __nv_bfloat16 l0 = __float2bfloat16(x.x - __bfloat162float(h0));
    __nv_bfloat16 l1 = __float2bfloat16(x.y - __bfloat162float(h1));
    __nv_bfloat16 l2 = __float2bfloat16(x.z - __bfloat162float(h2));
    __nv_bfloat16 l3 = __float2bfloat16(x.w - __bfloat162float(h3));
    ((__nv_bfloat162*)hp)[0] = __nv_bfloat162(h0, h1);
    ((__nv_bfloat162*)hp)[1] = __nv_bfloat162(h2, h3);
    ((__nv_bfloat162*)lp)[0] = __nv_bfloat162(l0, l1);
    ((__nv_bfloat162*)lp)[1] = __nv_bfloat162(l2, l3);
}

// ============================================================================
// Fused prepass: split src + {wq,wk,wv}->wqkv + w1 + w2 into bf16 hi/lo,
// pack {bq,bk,bv}->bqkv (fp32). Indices are float4 groups.
// ============================================================================
#define RA_TOTAL 7078656
__global__ __launch_bounds__(256)
void round_all(const float* __restrict__ src,
               const float* __restrict__ wq, const float* __restrict__ wk,
               const float* __restrict__ wv, const float* __restrict__ w1,
               const float* __restrict__ w2, const float* __restrict__ bq,
               const float* __restrict__ bk, const float* __restrict__ bv,
               __nv_bfloat16* __restrict__ srch, __nv_bfloat16* __restrict__ srcl,
               __nv_bfloat16* __restrict__ wqkvh, __nv_bfloat16* __restrict__ wqkvl,
               __nv_bfloat16* __restrict__ w1h, __nv_bfloat16* __restrict__ w1l,
               __nv_bfloat16* __restrict__ w2h, __nv_bfloat16* __restrict__ w2l,
               float* __restrict__ bqkv)
{
    long long i = (long long)blockIdx.x * 256 + threadIdx.x;
    if (i >= RA_TOTAL) return;
    if (i >= 7077888) {                 // bias pack, fp32 copy
        long long j = i - 7077888;      // 0..767
        const float* in;
        float* op;
        if (j < 256)      { in = bq + j * 4;         op = bqkv + j * 4; }
        else if (j < 512) { in = bk + (j - 256) * 4; op = bqkv + 1024 + (j - 256) * 4; }
        else              { in = bv + (j - 512) * 4; op = bqkv + 2048 + (j - 512) * 4; }
        *(float4*)op = *(const float4*)in;
        return;
    }
    const float* in;
    __nv_bfloat16 *hp, *lp;
    if (i < 4194304)      { in = src + i * 4; hp = srch + i * 4; lp = srcl + i * 4; }
    else if (i < 4456448) { long long j = i - 4194304; in = wq + j * 4; hp = wqkvh + j * 4; lp = wqkvl + j * 4; }
    else if (i < 4718592) { long long j = i - 4456448; in = wk + j * 4; hp = wqkvh + 1048576 + j * 4; lp = wqkvl + 1048576 + j * 4; }
    else if (i < 4980736) { long long j = i - 4718592; in = wv + j * 4; hp = wqkvh + 2097152 + j * 4; lp = wqkvl + 2097152 + j * 4; }
    else if (i < 6029312) { long long j = i - 4980736; in = w1 + j * 4; hp = w1h + j * 4; lp = w1l + j * 4; }
    else                  { long long j = i - 6029312; in = w2 + j * 4; hp = w2h + j * 4; lp = w2l + j * 4; }
    split_store4(*(const float4*)in, hp, lp);
}

// ============================================================================
// Split-bf16 TN GEMM: C = (Ah+Al)(Wh+Wl)^T ~= Ah Wh^T + Al Wh^T + Ah Wl^T
// Block 128x128, BK=32, 256 thr = 8 warps as 4(m:32-row) x 2(n:64-col);
// warp tile 32x64 via m16n16k16 bf16 wmma (ldmatrix operand path).
//   MODE 0: +bias(packed), tf32-round, scatter QKV -> q/k/v [B,H,S,d]
//   MODE 1: +bias, ReLU, write bf16 split pair (FFN1)
//   MODE 2: +bias, +extra fp32 residual, fp32 out (FFN2)
// ============================================================================
#define BM 128
#define BN 128
#define BK 32
#define LDB 40                       // bf16 elems per row (80B) - LDSM conflict-free
#define PLANE (128 * LDB)            // 5120 bf16
#define STG (4 * PLANE)              // Ah|Al|Bh|Bl per stage = 20480 bf16 = 40960 B
#define SPLIT_SMEM (2 * STG * (int)sizeof(__nv_bfloat16))   // 81920 B

template <int MODE>
__global__ __launch_bounds__(256, 2)
void gemm_split(const __nv_bfloat16* __restrict__ Ah, const __nv_bfloat16* __restrict__ Al,
                const __nv_bfloat16* __restrict__ Wh, const __nv_bfloat16* __restrict__ Wl,
                const float* __restrict__ bias, const float* __restrict__ extra,
                float* __restrict__ out0, float* __restrict__ out1, float* __restrict__ out2,
                __nv_bfloat16* __restrict__ oh, __nv_bfloat16* __restrict__ ol,
                int K, int N)
{
    extern __shared__ __nv_bfloat16 smp[];
    const int tid = threadIdx.x;
    const int wid = tid >> 5;
    const int lane = tid & 31;
    const int wm = wid & 3;      // 0..3 (32-row strips)
    const int wn = wid >> 2;     // 0..1 (64-col strips)

    wmma::fragment<wmma::accumulator, 16, 16, 16, float> acc[2][4];
#pragma unroll
    for (int i = 0; i < 2; i++)
#pragma unroll
        for (int j = 0; j < 4; j++)
            wmma::fill_fragment(acc[i][j], 0.0f);

    const __nv_bfloat16* Ahg = Ah + (size_t)blockIdx.y * BM * K;
    const __nv_bfloat16* Alg = Al + (size_t)blockIdx.y * BM * K;
    const __nv_bfloat16* Whg = Wh + (size_t)blockIdx.x * BN * K;
    const __nv_bfloat16* Wlg = Wl + (size_t)blockIdx.x * BN * K;

    // loader: each plane is 128 rows x 32 bf16 = 512 x 8-elem chunks
    auto load_stage = [&](int s, int kt) {
        __nv_bfloat16* st = smp + s * STG;
#pragma unroll
        for (int p = 0; p < 2; p++) {
            int c = tid + p * 256;            // 0..511
            int r = c >> 2, col = (c & 3) * 8;
            size_t go = (size_t)r * K + kt + col;
            unsigned so = r * LDB + col;
            cp16(st + so,             Ahg + go);
            cp16(st + PLANE + so,     Alg + go);
            cp16(st + 2 * PLANE + so, Whg + go);
            cp16(st + 3 * PLANE + so, Wlg + go);
        }
        asm volatile("cp.async.commit_group;\n");
    };

    const int T = K / BK;
    load_stage(0, 0);

    for (int t = 0; t < T; t++) {
        const int cur = t & 1;
        if (t + 1 < T) {
            load_stage(cur ^ 1, (t + 1) * BK);
            asm volatile("cp.async.wait_group 1;\n");
        } else {
            asm volatile("cp.async.wait_group 0;\n");
        }
        __syncthreads();

        const __nv_bfloat16* Ahs = smp + cur * STG;
        const __nv_bfloat16* Als = Ahs + PLANE;
        const __nv_bfloat16* Bhs = Ahs + 2 * PLANE;
        const __nv_bfloat16* Bls = Ahs + 3 * PLANE;

#pragma unroll
        for (int kk = 0; kk < BK; kk += 16) {
            wmma::fragment<wmma::matrix_a, 16, 16, 16, __nv_bfloat16, wmma::row_major> ah[2], al[2];
#pragma unroll
            for (int i = 0; i < 2; i++) {
                wmma::load_matrix_sync(ah[i], Ahs + (wm * 32 + i * 16) * LDB + kk, LDB);
                wmma::load_matrix_sync(al[i], Als + (wm * 32 + i * 16) * LDB + kk, LDB);
            }
#pragma unroll
            for (int j = 0; j < 4; j++) {
                wmma::fragment<wmma::matrix_b, 16, 16, 16, __nv_bfloat16, wmma::col_major> bh, bl;
                wmma::load_matrix_sync(bh, Bhs + (wn * 64 + j * 16) * LDB + kk, LDB);
                wmma::load_matrix_sync(bl, Bls + (wn * 64 + j * 16) * LDB + kk, LDB);
#pragma unroll
                for (int i = 0; i < 2; i++) {
                    wmma::mma_sync(acc[i][j], ah[i], bh, acc[i][j]);
                    wmma::mma_sync(acc[i][j], al[i], bh, acc[i][j]);
                    wmma::mma_sync(acc[i][j], ah[i], bl, acc[i][j]);
                }
            }
        }
        __syncthreads();
    }

    // Per-warp epilogue staging: 32x64 fp32 strip, stride 68.
    float* Cw = (float*)smp + wid * (32 * 68);
#pragma unroll
    for (int i = 0; i < 2; i++)
#pragma unroll
        for (int j = 0; j < 4; j++)
            wmma::store_matrix_sync(Cw + (i * 16) * 68 + j * 16, acc[i][j], 68,
                                    wmma::mem_row_major);
    __syncwarp();

    const int m = blockIdx.y * BM + wm * 32 + lane;
    const int n0 = blockIdx.x * BN + wn * 64;
    const float* crow = Cw + lane * 68;

#pragma unroll
    for (int c4 = 0; c4 < 16; c4++) {
        int n = n0 + c4 * 4;
        float4 c = *(float4*)(crow + c4 * 4);
        float4 bb = *(const float4*)(bias + n);
        c.x += bb.x; c.y += bb.y; c.z += bb.z; c.w += bb.w;
        if constexpr (MODE == 1) {
            c.x = fmaxf(c.x, 0.f); c.y = fmaxf(c.y, 0.f);
            c.z = fmaxf(c.z, 0.f); c.w = fmaxf(c.w, 0.f);
            split_store4(c, oh + (size_t)m * N + n, ol + (size_t)m * N + n);
        } else if constexpr (MODE == 2) {
            float4 e = *(const float4*)(extra + (size_t)m * N + n);
            c.x += e.x; c.y += e.y; c.z += e.z; c.w += e.w;
            *(float4*)(out0 + (size_t)m * N + n) = c;
        } else {
            c.x = tf32r(c.x); c.y = tf32r(c.y); c.z = tf32r(c.z); c.w = tf32r(c.w);
            int mat = n >> 10;
            int nl  = n & 1023;
            int h   = nl >> 6;
            int dd  = nl & (HDIM - 1);
            int bi  = m >> 12;
            int s   = m & (SEQ - 1);
            float* dst = (mat == 0) ? out0 : (mat == 1) ? out1 : out2;
            size_t o = (((size_t)bi * NHEAD + h) * SEQ + s) * HDIM + dd;
            *(float4*)(dst + o) = c;
        }
    }
}

// ============================================================================
// Windowed causal flash attention (tf32 wmma; register-Q, in-place acc)
// ============================================================================
#define ALD 72
#define ACCLD 68
#define ATTN_SMEM ((3 * 64 * ALD + 64 * ACCLD + 2 * 64) * (int)sizeof(float))

__global__ __launch_bounds__(256, 2)
void attn_kernel(const float* __restrict__ q, const float* __restrict__ k,
                 const float* __restrict__ v, float* __restrict__ out)
{
    const int idx = blockIdx.x;
    const int qc = idx & 7;
    const int w  = (idx >> 3) & 7;
    const int h  = (idx >> 6) & 15;
    const int b  = idx >> 10;

    extern __shared__ float sm[];
    float* k_s  = sm;
    float* v_s  = k_s + 64 * ALD;
    float* s_s  = v_s + 64 * ALD;
    float* accs = s_s + 64 * ALD;
    float* m_s  = accs + 64 * ACCLD;
    float* l_s  = m_s + 64;

    const int tid = threadIdx.x;
    const int wid = tid >> 5;
    const int wm  = wid & 1;
    const int wn  = wid >> 1;
    const size_t headbase = ((size_t)(b * NHEAD + h)) * SEQ * HDIM;
    const int q0 = w * WIN + qc * 64;

    const int tr = tid >> 4;
    const int tc = (tid & 15) << 2;

    wmma::fragment<wmma::matrix_a, 16, 16, 8, wmma::precision::tf32, wmma::row_major> a_q[2][8];
    {
        const float* qg = q + headbase + (size_t)q0 * HDIM;
#pragma unroll
        for (int i = 0; i < 2; i++)
#pragma unroll
            for (int ks = 0; ks < 8; ks++) {
                wmma::load_matrix_sync(a_q[i][ks],
                                       qg + (size_t)(wm * 32 + i * 16) * HDIM + ks * 8, HDIM);
#pragma unroll
                for (int e = 0; e < a_q[i][ks].num_elements; e++)
                    a_q[i][ks].x[e] = a_q[i][ks].x[e] * 0.125f;
            }
    }

#pragma unroll
    for (int p = 0; p < 4; p++) {
        int r = tr + p * 16;
        *(float4*)(accs + r * ACCLD + tc) = make_float4(0.f, 0.f, 0.f, 0.f);
    }
    if (tid < 64) { m_s[tid] = -1e30f; l_s[tid] = 0.f; }

    const int kstart = (w == 0) ? 0 : (w - 1) * WIN;
    const int kend   = q0 + 64;

    for (int kc = kstart; kc < kend; kc += 64) {
        __syncthreads();

        const float* kg = k + headbase + (size_t)kc * HDIM;
        const float* vg = v + headbase + (size_t)kc * HDIM;
#pragma unroll
        for (int p = 0; p < 4; p++) {
            int r = tr + p * 16;
            *(float4*)(k_s + r * ALD + tc) = *(const float4*)(kg + r * HDIM + tc);
            *(float4*)(v_s + r * ALD + tc) = *(const float4*)(vg + r * HDIM + tc);
        }
        __syncthreads();

        {
            wmma::fragment<wmma::accumulator, 16, 16, 8, float> sacc[2];
#pragma unroll
            for (int i = 0; i < 2; i++) wmma::fill_fragment(sacc[i], 0.0f);
#pragma unroll
            for (int ks = 0; ks < 8; ks++) {
                wmma::fragment<wmma::matrix_b, 16, 16, 8, wmma::precision::tf32, wmma::col_major> bf;
                wmma::load_matrix_sync(bf, k_s + (wn * 16) * ALD + ks * 8, ALD);
#pragma unroll
                for (int i = 0; i < 2; i++)
                    wmma::mma_sync(sacc[i], a_q[i][ks], bf, sacc[i]);
            }
#pragma unroll
            for (int i = 0; i < 2; i++)
                wmma::store_matrix_sync(s_s + (wm * 32 + i * 16) * ALD + wn * 16,
                                        sacc[i], ALD, wmma::mem_row_major);
        }
        __syncthreads();

        {
            const bool diag = (kc == q0);
            const int r  = tid >> 2;
            const int c0 = (tid & 3) << 4;
            float* srow = s_s + r * ALD + c0;
            float mloc = -1e30f;
            if (diag) {
#pragma unroll
                for (int t = 0; t < 16; t++) {
                    float sv = srow[t];
                    if (c0 + t > r) sv = -1e30f;
                    srow[t] = sv;
                    mloc = fmaxf(mloc, sv);
                }
            } else {
#pragma unroll
                for (int t = 0; t < 16; t++) mloc = fmaxf(mloc, srow[t]);
            }
            mloc = fmaxf(mloc, __shfl_xor_sync(0xffffffffu, mloc, 1));
            mloc = fmaxf(mloc, __shfl_xor_sync(0xffffffffu, mloc, 2));
            float mold = m_s[r];
            float mnew = fmaxf(mold, mloc);
            float ssum = 0.f;
#pragma unroll
            for (int t = 0; t < 16; t++) {
                float pz = tf32r(__expf(srow[t] - mnew));
                srow[t] = pz;
                ssum += pz;
            }
            ssum += __shfl_xor_sync(0xffffffffu, ssum, 1);
            ssum += __shfl_xor_sync(0xffffffffu, ssum, 2);
            float alpha = __expf(mold - mnew);
            if ((tid & 3) == 0) {
                m_s[r] = mnew;
                l_s[r] = l_s[r] * alpha + ssum;
            }
            float* arow = accs + r * ACCLD + c0;
#pragma unroll
            for (int t = 0; t < 4; t++) {
                float4 a4 = *(float4*)(arow + t * 4);
                a4.x *= alpha; a4.y *= alpha; a4.z *= alpha; a4.w *= alpha;
                *(float4*)(arow + t * 4) = a4;
            }
        }
        __syncthreads();

        {
            wmma::fragment<wmma::accumulator, 16, 16, 8, float> oacc[2];
#pragma unroll
            for (int i = 0; i < 2; i++)
                wmma::load_matrix_sync(oacc[i],
                                       accs + (wm * 32 + i * 16) * ACCLD + wn * 16,
                                       ACCLD, wmma::mem_row_major);
#pragma unroll
            for (int ks = 0; ks < 8; ks++) {
                wmma::fragment<wmma::matrix_b, 16, 16, 8, wmma::precision::tf32, wmma::row_major> bf;
                wmma::load_matrix_sync(bf, v_s + (ks * 8) * ALD + wn * 16, ALD);
#pragma unroll
                for (int i = 0; i < 2; i++) {
                    wmma::fragment<wmma::matrix_a, 16, 16, 8, wmma::precision::tf32, wmma::row_major> af;
                    wmma::load_matrix_sync(af, s_s + (wm * 32 + i * 16) * ALD + ks * 8, ALD);
                    wmma::mma_sync(oacc[i], af, bf, oacc[i]);
                }
            }
#pragma unroll
            for (int i = 0; i < 2; i++)
                wmma::store_matrix_sync(accs + (wm * 32 + i * 16) * ACCLD + wn * 16,
                                        oacc[i], ACCLD, wmma::mem_row_major);
        }
    }
    __syncthreads();

#pragma unroll
    for (int p = 0; p < 4; p++) {
        int r = tr + p * 16;
        float inv = 1.0f / l_s[r];
        float4 ac = *(float4*)(accs + r * ACCLD + tc);
        ac.x *= inv; ac.y *= inv; ac.z *= inv; ac.w *= inv;
        size_t o = ((size_t)(b * SEQ + q0 + r)) * DMODEL + h * HDIM + tc;
        *(float4*)(out + o) = ac;
    }
}

// ============================================================================
// LayerNorm over D=1024. SPLIT=1: also emit bf16 hi/lo planes (feeds GEMM).
// ============================================================================
template <int SPLIT>
__global__ __launch_bounds__(256)
void ln_kernel(const float* __restrict__ x, const float* __restrict__ gw,
               const float* __restrict__ bw, float* __restrict__ out,
               __nv_bfloat16* __restrict__ oh, __nv_bfloat16* __restrict__ ol)
{
    __shared__ float red[16];
    __shared__ float stats[2];
    const int row = blockIdx.x;
    const int tid = threadIdx.x;
    const float* xr = x + (size_t)row * DMODEL;

    float4 xv = *(const float4*)(xr + tid * 4);
    float s  = xv.x + xv.y + xv.z + xv.w;
    float s2 = xv.x * xv.x + xv.y * xv.y + xv.z * xv.z + xv.w * xv.w;
#pragma unroll
    for (int o = 16; o > 0; o >>= 1) {
        s  += __shfl_xor_sync(0xffffffffu, s, o);
        s2 += __shfl_xor_sync(0xffffffffu, s2, o);
    }
    if ((tid & 31) == 0) { red[tid >> 5] = s; red[8 + (tid >> 5)] = s2; }
    __syncthreads();
    if (tid == 0) {
        float ts = 0.f, ts2 = 0.f;
#pragma unroll
        for (int i = 0; i < 8; i++) { ts += red[i]; ts2 += red[8 + i]; }
        float mu  = ts * (1.0f / DMODEL);
        float var = ts2 * (1.0f / DMODEL) - mu * mu;
        stats[0] = mu;
        stats[1] = rsqrtf(var + 1e-5f);
    }
    __syncthreads();
    float mu = stats[0], rstd = stats[1];
    float4 gv = *(const float4*)(gw + tid * 4);
    float4 bv = *(const float4*)(bw + tid * 4);
    float4 ov;
    ov.x = (xv.x - mu) * rstd * gv.x + bv.x;
    ov.y = (xv.y - mu) * rstd * gv.y + bv.y;
    ov.z = (xv.z - mu) * rstd * gv.z + bv.z;
    ov.w = (xv.w - mu) * rstd * gv.w + bv.w;
    *(float4*)(out + (size_t)row * DMODEL + tid * 4) = ov;
    if constexpr (SPLIT == 1) {
        split_store4(ov, oh + (size_t)row * DMODEL + tid * 4,
                         ol + (size_t)row * DMODEL + tid * 4);
    }
}

// ============================================================================
extern "C" void kernel_launch(void* const* d_in, const int* in_sizes, int n_in,
                              void* d_out, int out_size)
{
    const float* src = (const float*)d_in[0];
    const float* wq  = (const float*)d_in[1];
    const float* bq  = (const float*)d_in[2];
    const float* wk  = (const float*)d_in[3];
    const float* bk  = (const float*)d_in[4];
    const float* wv  = (const float*)d_in[5];
    const float* bv  = (const float*)d_in[6];
    const float* w1  = (const float*)d_in[7];
    const float* b1  = (const float*)d_in[8];
    const float* w2  = (const float*)d_in[9];
    const float* b2  = (const float*)d_in[10];
    const float* g1  = (const float*)d_in[11];
    const float* be1 = (const float*)d_in[12];
    const float* g2  = (const float*)d_in[13];
    const float* be2 = (const float*)d_in[14];
    float* out = (float*)d_out;

    cudaFuncSetAttribute(gemm_split<0>, cudaFuncAttributeMaxDynamicSharedMemorySize, SPLIT_SMEM);
    cudaFuncSetAttribute(gemm_split<1>, cudaFuncAttributeMaxDynamicSharedMemorySize, SPLIT_SMEM);
    cudaFuncSetAttribute(gemm_split<2>, cudaFuncAttributeMaxDynamicSharedMemorySize, SPLIT_SMEM);
    cudaFuncSetAttribute(attn_kernel, cudaFuncAttributeMaxDynamicSharedMemorySize, ATTN_SMEM);

    float *q, *k, *v, *attn, *xln, *y, *bqkv;
    __nv_bfloat16 *srch, *srcl, *wqkvh, *wqkvl, *w1h, *w1l, *w2h, *w2l, *xh, *xl, *hh, *hl;
    cudaGetSymbolAddress((void**)&q,    g_q);
    cudaGetSymbolAddress((void**)&k,    g_k);
    cudaGetSymbolAddress((void**)&v,    g_v);
    cudaGetSymbolAddress((void**)&attn, g_attn);
    cudaGetSymbolAddress((void**)&xln,  g_xln);
    cudaGetSymbolAddress((void**)&y,    g_y);
    cudaGetSymbolAddress((void**)&bqkv, g_bqkv);
    cudaGetSymbolAddress((void**)&srch, g_srch);
    cudaGetSymbolAddress((void**)&srcl, g_srcl);
    cudaGetSymbolAddress((void**)&wqkvh, g_wqkvh);
    cudaGetSymbolAddress((void**)&wqkvl, g_wqkvl);
    cudaGetSymbolAddress((void**)&w1h, g_w1h);
    cudaGetSymbolAddress((void**)&w1l, g_w1l);
    cudaGetSymbolAddress((void**)&w2h, g_w2h);
    cudaGetSymbolAddress((void**)&w2l, g_w2l);
    cudaGetSymbolAddress((void**)&xh,  g_xh);
    cudaGetSymbolAddress((void**)&xl,  g_xl);
    cudaGetSymbolAddress((void**)&hh,  g_hh);
    cudaGetSymbolAddress((void**)&hl,  g_hl);

    // 0: fused split prepass
    round_all<<<(RA_TOTAL + 255) / 256, 256>>>(src, wq, wk, wv, w1, w2, bq, bk, bv,
                                               srch, srcl, wqkvh, wqkvl,
                                               w1h, w1l, w2h, w2l, bqkv);

    // 1: fused QKV GEMM (N = 3072)
    dim3 gQKV(3 * DMODEL / BN, MROWS / BM);        // (24, 128)
    gemm_split<0><<<gQKV, 256, SPLIT_SMEM>>>(srch, srcl, wqkvh, wqkvl, bqkv, nullptr,
                                             q, k, v, nullptr, nullptr,
                                             DMODEL, 3 * DMODEL);

    // 2: attention
    attn_kernel<<<BATCH * NHEAD * (SEQ / 64), 256, ATTN_SMEM>>>(q, k, v, attn);

    // 3: LN1 (fp32 + bf16 split out)
    ln_kernel<1><<<MROWS, 256>>>(attn, g1, be1, xln, xh, xl);

    // 4: FFN1 -> bf16 split h
    dim3 gF1(DFF / BN, MROWS / BM);                // (32, 128)
    gemm_split<1><<<gF1, 256, SPLIT_SMEM>>>(xh, xl, w1h, w1l, b1, nullptr,
                                            nullptr, nullptr, nullptr, hh, hl,
                                            DMODEL, DFF);

    // 5: FFN2 (+residual)
    dim3 gF2(DMODEL / BN, MROWS / BM);             // (8, 128)
    gemm_split<2><<<gF2, 256, SPLIT_SMEM>>>(hh, hl, w2h, w2l, b2, xln,
                                            y, nullptr, nullptr, nullptr, nullptr,
                                            DFF, DMODEL);

    // 6: LN2 -> out
    ln_kernel<0><<<MROWS, 256>>>(y, g2, be2, out, nullptr, nullptr);
}